// round 15
// baseline (speedup 1.0000x reference)
#include <cuda_runtime.h>
#include <cuda_fp16.h>
#include <cstdint>
#include <mma.h>

using namespace nvcuda;

// ---------------- problem constants ----------------
#define BATCH 1024
#define TSTEPS 256
#define DPART 64
#define ADIM 8
#define HDIM 256
#define CSIZE 4          // CTAs per cluster; each owns 192 cols (64 units x {r,z,p})
#define NCLUST 32        // clusters; each owns 32 batch rows
#define MROWS 32
#define NTHREADS 512     // 16 warps: 2 row groups x 8 col groups (24 cols each)

// SMEM layout (byte strides / offsets)
#define HS_STRIDE 528    // 264 halves (256 + 8 pad)
#define HSBUF (MROWS * HS_STRIDE)             // 16896 bytes per h buffer
#define PS_STRIDE 176    // 88 halves (80 + 8 pad)
#define WS_STRIDE 400    // 200 halves (192 + 8 pad)
#define SM_MBAR 0
#define SM_HS 128
#define SM_PS (SM_HS + 2 * HSBUF)             // 33920
#define SM_WH (SM_PS + MROWS * PS_STRIDE)     // 39552
#define SM_WX (SM_WH + 256 * WS_STRIDE)       // 141952
#define SMEM_BYTES (SM_WX + 80 * WS_STRIDE)   // 173952

// ---------------- device scratch ----------------
__device__ __half g_Whp[CSIZE * 256 * 192];  // h-weights, per-rank packed [rnk][k][192]
__device__ __half g_Wxp[CSIZE * 80 * 192];   // x-weights, per-rank packed [rnk][k][192]
__device__ __half g_hpp[2][BATCH * HDIM];    // final h (buffer 0 used by MLP)
__device__ float  g_W1t[2 * 288 * 256];
__device__ float  g_W2t[2 * 256 * 256];
__device__ float  g_mlp1[2 * BATCH * 256];
__device__ float  g_mlp2[2 * BATCH * 256];

// ---------------- PTX helpers ----------------
__device__ __forceinline__ unsigned smem_u32(const void* p) {
    unsigned a;
    asm("{ .reg .u64 t; cvta.to.shared.u64 t, %1; cvt.u32.u64 %0, t; }" : "=r"(a) : "l"(p));
    return a;
}
__device__ __forceinline__ float tanh_fast(float x) {
    float y;
    asm("tanh.approx.f32 %0, %1;" : "=f"(y) : "f"(x));
    return y;
}
__device__ __forceinline__ void ldsm_x4(unsigned r[4], unsigned addr) {
    asm volatile("ldmatrix.sync.aligned.m8n8.x4.shared.b16 {%0,%1,%2,%3}, [%4];"
        : "=r"(r[0]), "=r"(r[1]), "=r"(r[2]), "=r"(r[3]) : "r"(addr));
}
__device__ __forceinline__ void ldsm_x2_t(unsigned r[2], unsigned addr) {
    asm volatile("ldmatrix.sync.aligned.m8n8.x2.trans.shared.b16 {%0,%1}, [%2];"
        : "=r"(r[0]), "=r"(r[1]) : "r"(addr));
}
__device__ __forceinline__ void mma16816(float c[4], const unsigned a[4],
                                         unsigned b0, unsigned b1) {
    asm volatile("mma.sync.aligned.m16n8k16.row.col.f32.f16.f16.f32 "
        "{%0,%1,%2,%3}, {%4,%5,%6,%7}, {%8,%9}, {%0,%1,%2,%3};"
        : "+f"(c[0]), "+f"(c[1]), "+f"(c[2]), "+f"(c[3])
        : "r"(a[0]), "r"(a[1]), "r"(a[2]), "r"(a[3]), "r"(b0), "r"(b1));
}

#define MBAR_INIT(mbar, cnt) \
    asm volatile("mbarrier.init.shared.b64 [%0], %1;" :: "r"((unsigned)(mbar)), "r"((unsigned)(cnt)) : "memory")

__device__ __forceinline__ void mbar_arrive_peer(unsigned local_mbar, int d) {
    unsigned rem;
    asm("mapa.shared::cluster.u32 %0, %1, %2;" : "=r"(rem) : "r"(local_mbar), "r"(d));
    asm volatile("mbarrier.arrive.release.cluster.shared::cluster.b64 _, [%0];"
                 :: "r"(rem) : "memory");
}

__device__ __forceinline__ void dsmem_st_b32(unsigned local_off, int d, unsigned val) {
    unsigned rem;
    asm("mapa.shared::cluster.u32 %0, %1, %2;" : "=r"(rem) : "r"(local_off), "r"(d));
    asm volatile("st.shared::cluster.b32 [%0], %1;" :: "r"(rem), "r"(val) : "memory");
}

#define MBAR_WAIT_PARITY(mbar, par) do {                                             \
    unsigned _m = (unsigned)(mbar), _p = (unsigned)(par), _d;                        \
    asm volatile("{\n\t.reg .pred p;\n\t"                                            \
        "mbarrier.try_wait.parity.acquire.cluster.shared::cta.b64 p, [%1], %2;\n\t"  \
        "selp.b32 %0, 1, 0, p;\n\t}" : "=r"(_d) : "r"(_m), "r"(_p) : "memory");      \
    if (!_d) {                                                                       \
        asm volatile("{\n\t.reg .pred P1;\n\tWL_%=:\n\t"                             \
            "mbarrier.try_wait.parity.acquire.cluster.shared::cta.b64 P1, [%0], %1, 0x989680;\n\t" \
            "@P1 bra.uni WD_%=;\n\tbra.uni WL_%=;\n\tWD_%=:\n\t}"                    \
            :: "r"(_m), "r"(_p) : "memory");                                         \
    }                                                                                \
} while (0)

// ---------------- weight packing ----------------
// Rank slice: 192 cols = 8 col-groups x [r(8)|z(8)|p(8)] for 8 units each.
// col c: grp=c/24, rem=c%24, panel=rem/8, uu=rem%8, unit j = rnk*64 + grp*8 + uu.
__global__ void prep_weights(const float* __restrict__ Wi, const float* __restrict__ Wh) {
    int idx = blockIdx.x * blockDim.x + threadIdx.x;
    const int NH = CSIZE * 256 * 192;
    const int NX = CSIZE * 80 * 192;
    if (idx < NH) {
        int rnk = idx / (256 * 192);
        int rem = idx % (256 * 192);
        int k = rem / 192, c = rem % 192;
        int grp = c / 24, r2 = c % 24, panel = r2 / 8, uu = r2 % 8;
        int j = rnk * 64 + grp * 8 + uu;
        g_Whp[idx] = __float2half(Wh[k * 768 + panel * 256 + j]);
    } else if (idx < NH + NX) {
        int i2 = idx - NH;
        int rnk = i2 / (80 * 192);
        int rem = i2 % (80 * 192);
        int k = rem / 192, c = rem % 192;
        int grp = c / 24, r2 = c % 24, panel = r2 / 8, uu = r2 % 8;
        int j = rnk * 64 + grp * 8 + uu;
        float w = (k < 65) ? Wi[k * 768 + panel * 256 + j] : 0.0f;   // panel2 -> Wi_n
        g_Wxp[i2] = __float2half(w);
    }
}

__global__ void prep_mlp(const float* __restrict__ W1, const float* __restrict__ W2) {
    int idx = blockIdx.x * blockDim.x + threadIdx.x;
    const int N1 = 2 * 288 * 256;
    const int N2 = 2 * 256 * 256;
    if (idx < N1) {
        int c = idx / (288 * 256);
        int rem = idx % (288 * 256);
        int k = rem / 256, n = rem % 256;
        float w = (k < 265) ? W1[((size_t)c * 265 + k) * 256 + n] : 0.0f;
        g_W1t[idx] = wmma::__float_to_tf32(w);
    } else if (idx < N1 + N2) {
        g_W2t[idx - N1] = wmma::__float_to_tf32(W2[idx - N1]);
    }
}

// ---------------- persistent GRU: raw mma, 16 thin warps, DSMEM scatter ----------------
__global__ void __cluster_dims__(CSIZE, 1, 1) __launch_bounds__(NTHREADS, 1)
gru_reg(const float* __restrict__ particles,   // [B,T,DP]
        const float* __restrict__ pweights,    // [B,T]
        const float* __restrict__ bi,          // [768]
        const float* __restrict__ bhn)         // [256]
{
    extern __shared__ char smem[];
    const unsigned sb = smem_u32(smem);
    const unsigned mbar = sb + SM_MBAR;
    char* HsB = smem + SM_HS;    // [2][MROWS][HS_STRIDE]
    char* PsB = smem + SM_PS;

    const int tid  = threadIdx.x;
    const int lane = tid & 31;
    const int wid  = tid >> 5;
    const int wr   = wid & 1;       // row group: rows wr*16 .. wr*16+15
    const int wc2  = wid >> 1;      // col group: cols wc2*24 (0..7)
    const int rnk  = blockIdx.x & (CSIZE - 1);
    const int cl   = blockIdx.x >> 2;
    const int row0 = cl * MROWS;

    // ---- mbarrier init (arrivals per phase: 16 warps x 4 CTAs = 64) ----
    if (tid == 0) MBAR_INIT(mbar, 64);

    // ---- load weight slices into SMEM (once) ----
    for (int i = tid; i < 256 * 24; i += NTHREADS) {
        int r = i / 24, q = i % 24;
        *(uint4*)(smem + SM_WH + r * WS_STRIDE + q * 16) =
            *(const uint4*)(g_Whp + ((size_t)rnk * 256 + r) * 192 + q * 8);
    }
    for (int i = tid; i < 80 * 24; i += NTHREADS) {
        int r = i / 24, q = i % 24;
        *(uint4*)(smem + SM_WX + r * WS_STRIDE + q * 16) =
            *(const uint4*)(g_Wxp + ((size_t)rnk * 80 + r) * 192 + q * 8);
    }
    // ---- zero Hs buffer 0 (h_0 = 0) ----
    for (int i = tid; i < MROWS * 32; i += NTHREADS) {
        int r = i >> 5, q = i & 31;
        *(uint4*)(HsB + r * HS_STRIDE + q * 16) = make_uint4(0, 0, 0, 0);
    }
    // ---- zero Ps pad cols 64..87 ----
    for (int i = tid; i < MROWS * 3; i += NTHREADS) {
        int r = i / 3, q = i % 3;
        *(uint4*)(PsB + r * PS_STRIDE + 128 + q * 16) = make_uint4(0, 0, 0, 0);
    }
    // ---- fill Ps for t=0 ----
    for (int i = tid; i < MROWS * 16; i += NTHREADS) {
        int r = i >> 4, q = i & 15;
        float4 v = *(const float4*)(particles + ((size_t)(row0 + r) * TSTEPS + 0) * DPART + q * 4);
        __half2 h01 = __floats2half2_rn(v.x, v.y);
        __half2 h23 = __floats2half2_rn(v.z, v.w);
        *(uint2*)(PsB + r * PS_STRIDE + q * 8) =
            make_uint2(*(unsigned*)&h01, *(unsigned*)&h23);
    }
    if (tid < MROWS)
        *(__half*)(PsB + tid * PS_STRIDE + 128) =
            __float2half(pweights[(size_t)(row0 + tid) * TSTEPS + 0]);
    __syncthreads();
    // mbarriers + buffers ready cluster-wide before any remote op
    asm volatile("barrier.cluster.arrive.aligned;" ::: "memory");
    asm volatile("barrier.cluster.wait.aligned;" ::: "memory");

    // ---- per-thread ldmatrix base addresses ----
    const unsigned Ah = sb + SM_HS + (wr * 16 + (lane & 15)) * HS_STRIDE + (lane >> 4) * 16;
    const unsigned Ax = sb + SM_PS + (wr * 16 + (lane & 15)) * PS_STRIDE + (lane >> 4) * 16;
    // B loads are x2.trans (lanes 0-15 rows k0..15, 8 cols each)
    const unsigned Bh = sb + SM_WH + (lane & 15) * WS_STRIDE + wc2 * 48;
    const unsigned Bx = sb + SM_WX + (lane & 15) * WS_STRIDE + wc2 * 48;

    // ---- hoist step-invariant x-GEMM B fragments into registers (30 regs) ----
    unsigned bx[5][3][2];
#pragma unroll
    for (int kk = 0; kk < 5; ++kk)
#pragma unroll
        for (int pn = 0; pn < 3; ++pn)
            ldsm_x2_t(bx[kk][pn], Bx + kk * 16 * WS_STRIDE + pn * 16);

    // ---- per-thread epilogue constants (2 units) ----
    const int ub    = (lane & 3) * 2;
    const int jbase = rnk * 64 + wc2 * 8;
    const int j0    = jbase + ub;
    float bir[2], biz[2], bin[2], bhv[2];
#pragma unroll
    for (int s = 0; s < 2; ++s) {
        bir[s] = bi[j0 + s];
        biz[s] = bi[256 + j0 + s];
        bin[s] = bi[512 + j0 + s];
        bhv[s] = bhn[j0 + s];
    }

    for (int t = 0; t < TSTEPS; ++t) {
        const int p = t & 1;

        float accP[3][4];   // panels r,z,hpn (one n8 tile each)
        float accX[4];      // xn panel
#pragma unroll
        for (int pn = 0; pn < 3; ++pn)
#pragma unroll
            for (int e = 0; e < 4; ++e) accP[pn][e] = 0.0f;
#pragma unroll
        for (int e = 0; e < 4; ++e) accX[e] = 0.0f;

        // ---- x-GEMM (h-independent; B from registers; Ps covered by own-warp writes) ----
#pragma unroll
        for (int kk = 0; kk < 5; ++kk) {
            unsigned a[4];
            ldsm_x4(a, Ax + kk * 32);
            mma16816(accP[0], a, bx[kk][0][0], bx[kk][0][1]);
            mma16816(accP[1], a, bx[kk][1][0], bx[kk][1][1]);
            mma16816(accX,    a, bx[kk][2][0], bx[kk][2][1]);
        }

        // ---- wait: h_t fully scattered into own Hs[p] ----
        if (t > 0) MBAR_WAIT_PARITY(mbar, (t - 1) & 1);

        // ---- h-GEMM: accP += h_t[16,256] @ Wh_slice (24 cols) ----
        const unsigned AhP = Ah + (unsigned)(p * HSBUF);
#pragma unroll
        for (int kk = 0; kk < 16; ++kk) {
            unsigned a[4];
            ldsm_x4(a, AhP + kk * 32);
            const unsigned bbase = Bh + kk * 16 * WS_STRIDE;
            unsigned b0[2], b1[2], b2[2];
            ldsm_x2_t(b0, bbase);
            ldsm_x2_t(b1, bbase + 16);
            ldsm_x2_t(b2, bbase + 32);
            mma16816(accP[0], a, b0[0], b0[1]);
            mma16816(accP[1], a, b1[0], b1[1]);
            mma16816(accP[2], a, b2[0], b2[1]);
        }

        // ---- register gate epilogue + DSMEM scatter of h_{t+1} ----
        const unsigned hsOut = sb + SM_HS + (unsigned)((p ^ 1) * HSBUF);
#pragma unroll
        for (int rr = 0; rr < 2; ++rr) {
            const int rloc = wr * 16 + (lane >> 2) + rr * 8;
            __half2 ho2 = *(const __half2*)(HsB + p * HSBUF + rloc * HS_STRIDE + j0 * 2);
            float hov[2] = {__low2float(ho2), __high2float(ho2)};
            float hn[2];
#pragma unroll
            for (int s = 0; s < 2; ++s) {
                int e = rr * 2 + s;
                float rg = fmaf(0.5f, tanh_fast(0.5f * (accP[0][e] + bir[s])), 0.5f);
                float zg = fmaf(0.5f, tanh_fast(0.5f * (accP[1][e] + biz[s])), 0.5f);
                float a2 = (accX[e] + bin[s]) + rg * (accP[2][e] + bhv[s]);
                a2 = fminf(fmaxf(a2, -15.0f), 15.0f);
                float e2 = __expf(-2.0f * a2);
                float ng = __fdividef(1.0f - e2, 1.0f + e2);
                hn[s] = (1.0f - zg) * ng + zg * hov[s];
            }
            __half2 hv = __floats2half2_rn(hn[0], hn[1]);
            unsigned val = *(unsigned*)&hv;
            if (t < TSTEPS - 1) {
                unsigned off = hsOut + (unsigned)(rloc * HS_STRIDE + j0 * 2);
#pragma unroll
                for (int d = 0; d < CSIZE; ++d) dsmem_st_b32(off, d, val);
            } else {
                *(unsigned*)((char*)g_hpp[0] + ((size_t)(row0 + rloc) * HDIM + j0) * 2) = val;
            }
        }

        if (t < TSTEPS - 1) {
            // ---- refill Ps(t+1): EVERY warp writes all 16 rows of its wr group ----
            // (duplicated identical bytes; covers each warp's own pre-wait x-GEMM
            //  reads next step via program order — the R14 race fix)
#pragma unroll
            for (int k = 0; k < 8; ++k) {
                int item = lane + k * 32;          // 0..255
                int r = wr * 16 + (item >> 4);
                int q = item & 15;
                float4 v = *(const float4*)(particles +
                            ((size_t)(row0 + r) * TSTEPS + (t + 1)) * DPART + q * 4);
                __half2 h01 = __floats2half2_rn(v.x, v.y);
                __half2 h23 = __floats2half2_rn(v.z, v.w);
                *(uint2*)(PsB + r * PS_STRIDE + q * 8) =
                    make_uint2(*(unsigned*)&h01, *(unsigned*)&h23);
            }
            if (lane < 16) {
                int r = wr * 16 + lane;
                *(__half*)(PsB + r * PS_STRIDE + 128) =
                    __float2half(pweights[(size_t)(row0 + r) * TSTEPS + (t + 1)]);
            }
            // ---- release: stores (+refill) -> syncwarp -> lane0 release-arrives ----
            __syncwarp();
            if (lane == 0) {
#pragma unroll
                for (int d = 0; d < CSIZE; ++d) mbar_arrive_peer(mbar, d);
            }
        }
    }
}

// ---------------- MLP layers: tf32 wmma ----------------
__global__ void __launch_bounds__(256) mlp_layer_t(
    const float* __restrict__ action, const float* __restrict__ time_idx,
    const float* __restrict__ bias, int KP, int mode)
{
    __shared__ float As[64][40];
    __shared__ float Bs[32][72];
    __shared__ float stage[64][68];

    const int c = blockIdx.z;
    const int rowb = blockIdx.x * 64;
    const int colb = blockIdx.y * 64;
    const int tid = threadIdx.x;
    const int warp = tid >> 5;
    const int wr = warp & 3;
    const int wc = warp >> 2;

    wmma::fragment<wmma::accumulator, 16, 16, 8, float> acc[2];
    wmma::fill_fragment(acc[0], 0.0f);
    wmma::fill_fragment(acc[1], 0.0f);

    const float* Wsrc = (mode == 0) ? g_W1t + (size_t)c * 288 * 256
                                    : g_W2t + (size_t)c * 256 * 256;

    for (int k0 = 0; k0 < KP; k0 += 32) {
        for (int i = tid; i < 64 * 32; i += 256) {
            int r = i >> 5, k = i & 31;
            int d = k0 + k;
            float v = 0.0f;
            if (mode == 0) {
                if (d < 256)       v = __half2float(g_hpp[0][(size_t)(rowb + r) * HDIM + d]);
                else if (d < 264)  v = action[(rowb + r) * ADIM + (d - 256)];
                else if (d == 264) v = time_idx[rowb + r] * 0.01f;
            } else {
                v = g_mlp1[((size_t)c * BATCH + rowb + r) * 256 + d];
            }
            As[r][k] = wmma::__float_to_tf32(v);
        }
        for (int i = tid; i < 32 * 64; i += 256) {
            int kk = i >> 6, cc = i & 63;
            Bs[kk][cc] = Wsrc[(size_t)(k0 + kk) * 256 + colb + cc];
        }
        __syncthreads();
#pragma unroll
        for (int kk = 0; kk < 32; kk += 8) {
            wmma::fragment<wmma::matrix_a, 16, 16, 8, wmma::precision::tf32, wmma::row_major> af;
            wmma::load_matrix_sync(af, &As[wr * 16][kk], 40);
#pragma unroll
            for (int ct = 0; ct < 2; ct++) {
                wmma::fragment<wmma::matrix_b, 16, 16, 8, wmma::precision::tf32, wmma::row_major> bf;
                wmma::load_matrix_sync(bf, &Bs[kk][wc * 32 + ct * 16], 72);
                wmma::mma_sync(acc[ct], af, bf, acc[ct]);
            }
        }
        __syncthreads();
    }

#pragma unroll
    for (int ct = 0; ct < 2; ct++)
        wmma::store_matrix_sync(&stage[wr * 16][wc * 32 + ct * 16], acc[ct], 68,
                                wmma::mem_row_major);
    __syncthreads();

    float* dst = (mode == 0) ? g_mlp1 : g_mlp2;
    for (int i = tid; i < 64 * 64; i += 256) {
        int r = i >> 6, col = i & 63;
        float v = stage[r][col] + bias[c * 256 + colb + col];
        dst[((size_t)c * BATCH + rowb + r) * 256 + colb + col] = fmaxf(v, 0.0f);
    }
}

// ---------------- final projection ----------------
__global__ void mlp_out(const float* __restrict__ W3, const float* __restrict__ b3,
                        float* __restrict__ out)
{
    int gw   = (blockIdx.x * blockDim.x + threadIdx.x) >> 5;
    int lane = threadIdx.x & 31;
    if (gw >= 2 * BATCH) return;
    int c = gw >> 10;
    int b = gw & 1023;
    const float* v = g_mlp2 + ((size_t)c * BATCH + b) * 256;
    const float* w = W3 + (size_t)c * 256;
    float s = 0.0f;
    for (int i = lane; i < 256; i += 32) s += v[i] * w[i];
#pragma unroll
    for (int o = 16; o; o >>= 1) s += __shfl_xor_sync(0xffffffffu, s, o);
    if (lane == 0) out[b * 2 + c] = s + b3[c];
}

// ---------------- launch ----------------
extern "C" void kernel_launch(void* const* d_in, const int* in_sizes, int n_in,
                              void* d_out, int out_size)
{
    const float* particles = (const float*)d_in[0];
    const float* weights   = (const float*)d_in[1];
    const float* action    = (const float*)d_in[2];
    const float* time_idx  = (const float*)d_in[3];
    const float* Wi        = (const float*)d_in[4];
    const float* bi        = (const float*)d_in[5];
    const float* Wh        = (const float*)d_in[6];
    const float* bhn       = (const float*)d_in[7];
    const float* W1        = (const float*)d_in[8];
    const float* b1        = (const float*)d_in[9];
    const float* W2        = (const float*)d_in[10];
    const float* b2        = (const float*)d_in[11];
    const float* W3        = (const float*)d_in[12];
    const float* b3        = (const float*)d_in[13];
    float* out = (float*)d_out;

    cudaFuncSetAttribute(gru_reg, cudaFuncAttributeMaxDynamicSharedMemorySize, SMEM_BYTES);

    const int NWT = CSIZE * 256 * 192 + CSIZE * 80 * 192;
    prep_weights<<<(NWT + 255) / 256, 256>>>(Wi, Wh);                        // idx 0
    prep_mlp<<<(2 * 288 * 256 + 2 * 256 * 256 + 255) / 256, 256>>>(W1, W2);  // idx 1
    prep_mlp<<<1, 32>>>(W1, W2);  // idx 2 (tiny repeat; keeps gru at idx 3)
    gru_reg<<<NCLUST * CSIZE, NTHREADS, SMEM_BYTES>>>(particles, weights, bi, bhn); // idx 3 (ncu)

    mlp_layer_t<<<dim3(16, 4, 2), 256>>>(action, time_idx, b1, 288, 0);
    mlp_layer_t<<<dim3(16, 4, 2), 256>>>(action, time_idx, b2, 256, 1);
    mlp_out<<<(2 * BATCH * 32 + 255) / 256, 256>>>(W3, b3, out);
}

// round 16
// speedup vs baseline: 1.1454x; 1.1454x over previous
#include <cuda_runtime.h>
#include <cuda_fp16.h>
#include <cstdint>
#include <mma.h>

using namespace nvcuda;

// ---------------- problem constants ----------------
#define BATCH 1024
#define TSTEPS 256
#define DPART 64
#define ADIM 8
#define HDIM 256
#define CSIZE 4          // CTAs per cluster; each owns 192 cols (64 units x {r,z,p})
#define NCLUST 32        // clusters; each owns 32 batch rows
#define MROWS 32
#define NTHREADS 256     // 8 warps: 2 row groups x 4 col groups (48 cols each)

// SMEM layout (byte strides / offsets)
#define HS_STRIDE 528    // 264 halves (256 + 8 pad)
#define HSBUF (MROWS * HS_STRIDE)             // 16896 bytes per h buffer
#define PS_STRIDE 176    // 88 halves (80 + 8 pad)
#define WS_STRIDE 400    // 200 halves (192 + 8 pad)
#define SM_MBAR 0        // 4 mbarriers, 8 bytes each (per source CTA)
#define SM_HS 128
#define SM_PS (SM_HS + 2 * HSBUF)             // 33920
#define SM_WH (SM_PS + MROWS * PS_STRIDE)     // 39552
#define SM_WX (SM_WH + 256 * WS_STRIDE)       // 141952
#define SMEM_BYTES (SM_WX + 80 * WS_STRIDE)   // 173952

// ---------------- device scratch ----------------
__device__ __half g_Whp[CSIZE * 256 * 192];  // h-weights, per-rank packed [rnk][k][192]
__device__ __half g_Wxp[CSIZE * 80 * 192];   // x-weights, per-rank packed [rnk][k][192]
__device__ __half g_hpp[2][BATCH * HDIM];    // final h (buffer 0 used by MLP)
__device__ float  g_W1t[2 * 288 * 256];
__device__ float  g_W2t[2 * 256 * 256];
__device__ float  g_mlp1[2 * BATCH * 256];
__device__ float  g_mlp2[2 * BATCH * 256];

// ---------------- PTX helpers ----------------
__device__ __forceinline__ unsigned smem_u32(const void* p) {
    unsigned a;
    asm("{ .reg .u64 t; cvta.to.shared.u64 t, %1; cvt.u32.u64 %0, t; }" : "=r"(a) : "l"(p));
    return a;
}
__device__ __forceinline__ float tanh_fast(float x) {
    float y;
    asm("tanh.approx.f32 %0, %1;" : "=f"(y) : "f"(x));
    return y;
}
__device__ __forceinline__ void ldsm_x4(unsigned r[4], unsigned addr) {
    asm volatile("ldmatrix.sync.aligned.m8n8.x4.shared.b16 {%0,%1,%2,%3}, [%4];"
        : "=r"(r[0]), "=r"(r[1]), "=r"(r[2]), "=r"(r[3]) : "r"(addr));
}
__device__ __forceinline__ void ldsm_x4_t(unsigned r[4], unsigned addr) {
    asm volatile("ldmatrix.sync.aligned.m8n8.x4.trans.shared.b16 {%0,%1,%2,%3}, [%4];"
        : "=r"(r[0]), "=r"(r[1]), "=r"(r[2]), "=r"(r[3]) : "r"(addr));
}
__device__ __forceinline__ void mma16816(float c[4], const unsigned a[4],
                                         unsigned b0, unsigned b1) {
    asm volatile("mma.sync.aligned.m16n8k16.row.col.f32.f16.f16.f32 "
        "{%0,%1,%2,%3}, {%4,%5,%6,%7}, {%8,%9}, {%0,%1,%2,%3};"
        : "+f"(c[0]), "+f"(c[1]), "+f"(c[2]), "+f"(c[3])
        : "r"(a[0]), "r"(a[1]), "r"(a[2]), "r"(a[3]), "r"(b0), "r"(b1));
}

#define MBAR_INIT(mbar, cnt) \
    asm volatile("mbarrier.init.shared.b64 [%0], %1;" :: "r"((unsigned)(mbar)), "r"((unsigned)(cnt)) : "memory")

// remote release-arrive on peer d's mbarrier at the SAME SMEM offset
__device__ __forceinline__ void mbar_arrive_peer(unsigned local_mbar, int d) {
    unsigned rem;
    asm("mapa.shared::cluster.u32 %0, %1, %2;" : "=r"(rem) : "r"(local_mbar), "r"(d));
    asm volatile("mbarrier.arrive.release.cluster.shared::cluster.b64 _, [%0];"
                 :: "r"(rem) : "memory");
}

__device__ __forceinline__ void dsmem_st_b32(unsigned local_off, int d, unsigned val) {
    unsigned rem;
    asm("mapa.shared::cluster.u32 %0, %1, %2;" : "=r"(rem) : "r"(local_off), "r"(d));
    asm volatile("st.shared::cluster.b32 [%0], %1;" :: "r"(rem), "r"(val) : "memory");
}

#define MBAR_WAIT_PARITY(mbar, par) do {                                             \
    unsigned _m = (unsigned)(mbar), _p = (unsigned)(par), _d;                        \
    asm volatile("{\n\t.reg .pred p;\n\t"                                            \
        "mbarrier.try_wait.parity.acquire.cluster.shared::cta.b64 p, [%1], %2;\n\t"  \
        "selp.b32 %0, 1, 0, p;\n\t}" : "=r"(_d) : "r"(_m), "r"(_p) : "memory");      \
    if (!_d) {                                                                       \
        asm volatile("{\n\t.reg .pred P1;\n\tWL_%=:\n\t"                             \
            "mbarrier.try_wait.parity.acquire.cluster.shared::cta.b64 P1, [%0], %1, 0x989680;\n\t" \
            "@P1 bra.uni WD_%=;\n\tbra.uni WL_%=;\n\tWD_%=:\n\t}"                    \
            :: "r"(_m), "r"(_p) : "memory");                                         \
    }                                                                                \
} while (0)

// ---------------- weight packing ----------------
// Rank slice: 192 cols = 4 col-groups x [r(16)|z(16)|p(16)] for 16 units each.
__global__ void prep_weights(const float* __restrict__ Wi, const float* __restrict__ Wh) {
    int idx = blockIdx.x * blockDim.x + threadIdx.x;
    const int NH = CSIZE * 256 * 192;
    const int NX = CSIZE * 80 * 192;
    if (idx < NH) {
        int rnk = idx / (256 * 192);
        int rem = idx % (256 * 192);
        int k = rem / 192, c = rem % 192;
        int wcg = c / 48, r2 = c % 48, panel = r2 / 16, uu = r2 % 16;
        int j = rnk * 64 + wcg * 16 + uu;
        g_Whp[idx] = __float2half(Wh[k * 768 + panel * 256 + j]);
    } else if (idx < NH + NX) {
        int i2 = idx - NH;
        int rnk = i2 / (80 * 192);
        int rem = i2 % (80 * 192);
        int k = rem / 192, c = rem % 192;
        int wcg = c / 48, r2 = c % 48, panel = r2 / 16, uu = r2 % 16;
        int j = rnk * 64 + wcg * 16 + uu;
        float w = (k < 65) ? Wi[k * 768 + panel * 256 + j] : 0.0f;
        g_Wxp[i2] = __float2half(w);
    }
}

__global__ void prep_mlp(const float* __restrict__ W1, const float* __restrict__ W2) {
    int idx = blockIdx.x * blockDim.x + threadIdx.x;
    const int N1 = 2 * 288 * 256;
    const int N2 = 2 * 256 * 256;
    if (idx < N1) {
        int c = idx / (288 * 256);
        int rem = idx % (288 * 256);
        int k = rem / 256, n = rem % 256;
        float w = (k < 265) ? W1[((size_t)c * 265 + k) * 256 + n] : 0.0f;
        g_W1t[idx] = wmma::__float_to_tf32(w);
    } else if (idx < N1 + N2) {
        g_W2t[idx - N1] = wmma::__float_to_tf32(W2[idx - N1]);
    }
}

// ---------------- persistent GRU: raw mma, per-source mbarriers, h reg-carry ----------------
__global__ void __cluster_dims__(CSIZE, 1, 1) __launch_bounds__(NTHREADS, 1)
gru_reg(const float* __restrict__ particles,   // [B,T,DP]
        const float* __restrict__ pweights,    // [B,T]
        const float* __restrict__ bi,          // [768]
        const float* __restrict__ bhn)         // [256]
{
    extern __shared__ char smem[];
    const unsigned sb = smem_u32(smem);
    char* HsB = smem + SM_HS;    // [2][MROWS][HS_STRIDE]
    char* PsB = smem + SM_PS;

    const int tid  = threadIdx.x;
    const int lane = tid & 31;
    const int wid  = tid >> 5;
    const int wr   = wid & 1;       // row group: rows wr*16 .. wr*16+15
    const int wc   = wid >> 1;      // col group: cols wc*48 (0..3)
    const int rnk  = blockIdx.x & (CSIZE - 1);
    const int cl   = blockIdx.x >> 2;
    const int row0 = cl * MROWS;

    // ---- mbarrier init: 4 per-source barriers, 8 arrivals each (source's warps) ----
    if (tid == 0) {
#pragma unroll
        for (int d = 0; d < CSIZE; ++d) MBAR_INIT(sb + SM_MBAR + d * 8, 8);
    }

    // ---- load weight slices into SMEM (once) ----
    for (int i = tid; i < 256 * 24; i += NTHREADS) {
        int r = i / 24, q = i % 24;
        *(uint4*)(smem + SM_WH + r * WS_STRIDE + q * 16) =
            *(const uint4*)(g_Whp + ((size_t)rnk * 256 + r) * 192 + q * 8);
    }
    for (int i = tid; i < 80 * 24; i += NTHREADS) {
        int r = i / 24, q = i % 24;
        *(uint4*)(smem + SM_WX + r * WS_STRIDE + q * 16) =
            *(const uint4*)(g_Wxp + ((size_t)rnk * 80 + r) * 192 + q * 8);
    }
    // ---- zero Hs buffer 0 (h_0 = 0) ----
    for (int i = tid; i < MROWS * 32; i += NTHREADS) {
        int r = i >> 5, q = i & 31;
        *(uint4*)(HsB + r * HS_STRIDE + q * 16) = make_uint4(0, 0, 0, 0);
    }
    // ---- zero Ps pad cols 64..87 ----
    for (int i = tid; i < MROWS * 3; i += NTHREADS) {
        int r = i / 3, q = i % 3;
        *(uint4*)(PsB + r * PS_STRIDE + 128 + q * 16) = make_uint4(0, 0, 0, 0);
    }
    // ---- fill Ps for t=0 ----
    for (int i = tid; i < MROWS * 16; i += NTHREADS) {
        int r = i >> 4, q = i & 15;
        float4 v = *(const float4*)(particles + ((size_t)(row0 + r) * TSTEPS + 0) * DPART + q * 4);
        __half2 h01 = __floats2half2_rn(v.x, v.y);
        __half2 h23 = __floats2half2_rn(v.z, v.w);
        *(uint2*)(PsB + r * PS_STRIDE + q * 8) =
            make_uint2(*(unsigned*)&h01, *(unsigned*)&h23);
    }
    if (tid < MROWS)
        *(__half*)(PsB + tid * PS_STRIDE + 128) =
            __float2half(pweights[(size_t)(row0 + tid) * TSTEPS + 0]);
    __syncthreads();
    // mbarriers + buffers ready cluster-wide before any remote op
    asm volatile("barrier.cluster.arrive.aligned;" ::: "memory");
    asm volatile("barrier.cluster.wait.aligned;" ::: "memory");

    // ---- per-thread ldmatrix base addresses ----
    const unsigned Ah = sb + SM_HS + (wr * 16 + (lane & 15)) * HS_STRIDE + (lane >> 4) * 16;
    const unsigned Ax = sb + SM_PS + (wr * 16 + (lane & 15)) * PS_STRIDE + (lane >> 4) * 16;
    const unsigned Bh = sb + SM_WH + (lane & 15) * WS_STRIDE + (wc * 48 + (lane >> 4) * 8) * 2;
    const unsigned Bx = sb + SM_WX + (lane & 15) * WS_STRIDE + (wc * 48 + (lane >> 4) * 8) * 2;

    // ---- hoist step-invariant x-GEMM B fragments into registers ----
    unsigned bx[5][3][4];
#pragma unroll
    for (int kk = 0; kk < 5; ++kk)
#pragma unroll
        for (int pn = 0; pn < 3; ++pn)
            ldsm_x4_t(bx[kk][pn], Bx + kk * 16 * WS_STRIDE + pn * 32);

    // ---- per-thread epilogue constants ----
    const int ub    = (lane & 3) * 2;
    const int jbase = rnk * 64 + wc * 16;
    float bir[2][2], biz[2][2], bin[2][2], bhv[2][2];
#pragma unroll
    for (int nh = 0; nh < 2; ++nh)
#pragma unroll
        for (int pa = 0; pa < 2; ++pa) {
            int j = jbase + ub + nh * 8 + pa;
            bir[nh][pa] = bi[j];
            biz[nh][pa] = bi[256 + j];
            bin[nh][pa] = bi[512 + j];
            bhv[nh][pa] = bhn[j];
        }

    // ---- register carry of this thread's own h values (h_0 = 0) ----
    unsigned prevv[2][2] = {{0u, 0u}, {0u, 0u}};   // [nh][rr] packed half2

    for (int t = 0; t < TSTEPS; ++t) {
        const int p = t & 1;

        float accP[3][2][4];   // panels r,z,hpn x n8-halves x 4 elems
        float accX[2][4];      // xn panel
#pragma unroll
        for (int pn = 0; pn < 3; ++pn)
#pragma unroll
            for (int nh = 0; nh < 2; ++nh)
#pragma unroll
                for (int e = 0; e < 4; ++e) accP[pn][nh][e] = 0.0f;
#pragma unroll
        for (int nh = 0; nh < 2; ++nh)
#pragma unroll
            for (int e = 0; e < 4; ++e) accX[nh][e] = 0.0f;

        // ---- x-GEMM (h-independent; B from registers) ----
#pragma unroll
        for (int kk = 0; kk < 5; ++kk) {
            unsigned a[4];
            ldsm_x4(a, Ax + kk * 32);
#pragma unroll
            for (int pn = 0; pn < 3; ++pn) {
                float* c0 = (pn < 2) ? accP[pn][0] : accX[0];
                float* c1 = (pn < 2) ? accP[pn][1] : accX[1];
                mma16816(c0, a, bx[kk][pn][0], bx[kk][pn][1]);
                mma16816(c1, a, bx[kk][pn][2], bx[kk][pn][3]);
            }
        }

        // ---- h-GEMM, pipelined per source slice: wait mbar[chunk] then its 4 K-chunks ----
        const unsigned AhP = Ah + (unsigned)(p * HSBUF);
#pragma unroll
        for (int c4 = 0; c4 < CSIZE; ++c4) {
            const int chunk = (rnk + c4) & (CSIZE - 1);
            if (t > 0) MBAR_WAIT_PARITY(sb + SM_MBAR + chunk * 8, (t - 1) & 1);
#pragma unroll
            for (int k2 = 0; k2 < 4; ++k2) {
                const int kk = chunk * 4 + k2;
                unsigned a[4];
                ldsm_x4(a, AhP + kk * 32);
#pragma unroll
                for (int pn = 0; pn < 3; ++pn) {
                    unsigned b[4];
                    ldsm_x4_t(b, Bh + kk * 16 * WS_STRIDE + pn * 32);
                    mma16816(accP[pn][0], a, b[0], b[1]);
                    mma16816(accP[pn][1], a, b[2], b[3]);
                }
            }
        }

        // ---- register gate epilogue (h_old from register carry) + DSMEM scatter ----
        const unsigned hsOut = sb + SM_HS + (unsigned)((p ^ 1) * HSBUF);
#pragma unroll
        for (int nh = 0; nh < 2; ++nh) {
            const int jc = jbase + ub + nh * 8;
#pragma unroll
            for (int rr = 0; rr < 2; ++rr) {
                const int rloc = wr * 16 + (lane >> 2) + rr * 8;
                __half2 ho2 = *(__half2*)&prevv[nh][rr];
                float hov[2] = {__low2float(ho2), __high2float(ho2)};
                float hn[2];
#pragma unroll
                for (int s = 0; s < 2; ++s) {
                    int e = rr * 2 + s;
                    float rg = fmaf(0.5f, tanh_fast(0.5f * (accP[0][nh][e] + bir[nh][s])), 0.5f);
                    float zg = fmaf(0.5f, tanh_fast(0.5f * (accP[1][nh][e] + biz[nh][s])), 0.5f);
                    float a2 = (accX[nh][e] + bin[nh][s]) + rg * (accP[2][nh][e] + bhv[nh][s]);
                    a2 = fminf(fmaxf(a2, -15.0f), 15.0f);
                    float e2 = __expf(-2.0f * a2);
                    float ng = __fdividef(1.0f - e2, 1.0f + e2);
                    hn[s] = (1.0f - zg) * ng + zg * hov[s];
                }
                __half2 hv = __floats2half2_rn(hn[0], hn[1]);
                unsigned val = *(unsigned*)&hv;
                prevv[nh][rr] = val;
                if (t < TSTEPS - 1) {
                    unsigned off = hsOut + (unsigned)(rloc * HS_STRIDE + jc * 2);
#pragma unroll
                    for (int d = 0; d < CSIZE; ++d) dsmem_st_b32(off, d, val);
                } else {
                    *(unsigned*)((char*)g_hpp[0] + ((size_t)(row0 + rloc) * HDIM + jc) * 2) = val;
                }
            }
        }

        if (t < TSTEPS - 1) {
            // ---- refill Ps(t+1): every warp writes all 16 rows of its wr group ----
            // (duplicated identical bytes; covers own pre-wait x-GEMM reads next step)
#pragma unroll
            for (int k = 0; k < 8; ++k) {
                int item = lane + k * 32;          // 0..255
                int r = wr * 16 + (item >> 4);
                int q = item & 15;
                float4 v = *(const float4*)(particles +
                            ((size_t)(row0 + r) * TSTEPS + (t + 1)) * DPART + q * 4);
                __half2 h01 = __floats2half2_rn(v.x, v.y);
                __half2 h23 = __floats2half2_rn(v.z, v.w);
                *(uint2*)(PsB + r * PS_STRIDE + q * 8) =
                    make_uint2(*(unsigned*)&h01, *(unsigned*)&h23);
            }
            if (lane < 16) {
                int r = wr * 16 + lane;
                *(__half*)(PsB + r * PS_STRIDE + 128) =
                    __float2half(pweights[(size_t)(row0 + r) * TSTEPS + (t + 1)]);
            }
            // ---- release: stores (+refill) -> syncwarp -> lane0 arrives on slot rnk
            //      of all 4 CTAs ("source rnk's slice of h_{t+1} is stored") ----
            __syncwarp();
            if (lane == 0) {
#pragma unroll
                for (int d = 0; d < CSIZE; ++d)
                    mbar_arrive_peer(sb + SM_MBAR + rnk * 8, d);
            }
        }
    }
}

// ---------------- MLP layers: tf32 wmma ----------------
__global__ void __launch_bounds__(256) mlp_layer_t(
    const float* __restrict__ action, const float* __restrict__ time_idx,
    const float* __restrict__ bias, int KP, int mode)
{
    __shared__ float As[64][40];
    __shared__ float Bs[32][72];
    __shared__ float stage[64][68];

    const int c = blockIdx.z;
    const int rowb = blockIdx.x * 64;
    const int colb = blockIdx.y * 64;
    const int tid = threadIdx.x;
    const int warp = tid >> 5;
    const int wr = warp & 3;
    const int wc = warp >> 2;

    wmma::fragment<wmma::accumulator, 16, 16, 8, float> acc[2];
    wmma::fill_fragment(acc[0], 0.0f);
    wmma::fill_fragment(acc[1], 0.0f);

    const float* Wsrc = (mode == 0) ? g_W1t + (size_t)c * 288 * 256
                                    : g_W2t + (size_t)c * 256 * 256;

    for (int k0 = 0; k0 < KP; k0 += 32) {
        for (int i = tid; i < 64 * 32; i += 256) {
            int r = i >> 5, k = i & 31;
            int d = k0 + k;
            float v = 0.0f;
            if (mode == 0) {
                if (d < 256)       v = __half2float(g_hpp[0][(size_t)(rowb + r) * HDIM + d]);
                else if (d < 264)  v = action[(rowb + r) * ADIM + (d - 256)];
                else if (d == 264) v = time_idx[rowb + r] * 0.01f;
            } else {
                v = g_mlp1[((size_t)c * BATCH + rowb + r) * 256 + d];
            }
            As[r][k] = wmma::__float_to_tf32(v);
        }
        for (int i = tid; i < 32 * 64; i += 256) {
            int kk = i >> 6, cc = i & 63;
            Bs[kk][cc] = Wsrc[(size_t)(k0 + kk) * 256 + colb + cc];
        }
        __syncthreads();
#pragma unroll
        for (int kk = 0; kk < 32; kk += 8) {
            wmma::fragment<wmma::matrix_a, 16, 16, 8, wmma::precision::tf32, wmma::row_major> af;
            wmma::load_matrix_sync(af, &As[wr * 16][kk], 40);
#pragma unroll
            for (int ct = 0; ct < 2; ct++) {
                wmma::fragment<wmma::matrix_b, 16, 16, 8, wmma::precision::tf32, wmma::row_major> bf;
                wmma::load_matrix_sync(bf, &Bs[kk][wc * 32 + ct * 16], 72);
                wmma::mma_sync(acc[ct], af, bf, acc[ct]);
            }
        }
        __syncthreads();
    }

#pragma unroll
    for (int ct = 0; ct < 2; ct++)
        wmma::store_matrix_sync(&stage[wr * 16][wc * 32 + ct * 16], acc[ct], 68,
                                wmma::mem_row_major);
    __syncthreads();

    float* dst = (mode == 0) ? g_mlp1 : g_mlp2;
    for (int i = tid; i < 64 * 64; i += 256) {
        int r = i >> 6, col = i & 63;
        float v = stage[r][col] + bias[c * 256 + colb + col];
        dst[((size_t)c * BATCH + rowb + r) * 256 + colb + col] = fmaxf(v, 0.0f);
    }
}

// ---------------- final projection ----------------
__global__ void mlp_out(const float* __restrict__ W3, const float* __restrict__ b3,
                        float* __restrict__ out)
{
    int gw   = (blockIdx.x * blockDim.x + threadIdx.x) >> 5;
    int lane = threadIdx.x & 31;
    if (gw >= 2 * BATCH) return;
    int c = gw >> 10;
    int b = gw & 1023;
    const float* v = g_mlp2 + ((size_t)c * BATCH + b) * 256;
    const float* w = W3 + (size_t)c * 256;
    float s = 0.0f;
    for (int i = lane; i < 256; i += 32) s += v[i] * w[i];
#pragma unroll
    for (int o = 16; o; o >>= 1) s += __shfl_xor_sync(0xffffffffu, s, o);
    if (lane == 0) out[b * 2 + c] = s + b3[c];
}

// ---------------- launch ----------------
extern "C" void kernel_launch(void* const* d_in, const int* in_sizes, int n_in,
                              void* d_out, int out_size)
{
    const float* particles = (const float*)d_in[0];
    const float* weights   = (const float*)d_in[1];
    const float* action    = (const float*)d_in[2];
    const float* time_idx  = (const float*)d_in[3];
    const float* Wi        = (const float*)d_in[4];
    const float* bi        = (const float*)d_in[5];
    const float* Wh        = (const float*)d_in[6];
    const float* bhn       = (const float*)d_in[7];
    const float* W1        = (const float*)d_in[8];
    const float* b1        = (const float*)d_in[9];
    const float* W2        = (const float*)d_in[10];
    const float* b2        = (const float*)d_in[11];
    const float* W3        = (const float*)d_in[12];
    const float* b3        = (const float*)d_in[13];
    float* out = (float*)d_out;

    cudaFuncSetAttribute(gru_reg, cudaFuncAttributeMaxDynamicSharedMemorySize, SMEM_BYTES);

    const int NWT = CSIZE * 256 * 192 + CSIZE * 80 * 192;
    prep_weights<<<(NWT + 255) / 256, 256>>>(Wi, Wh);                        // idx 0
    prep_mlp<<<(2 * 288 * 256 + 2 * 256 * 256 + 255) / 256, 256>>>(W1, W2);  // idx 1
    prep_mlp<<<1, 32>>>(W1, W2);  // idx 2 (tiny repeat; keeps gru at idx 3)
    gru_reg<<<NCLUST * CSIZE, NTHREADS, SMEM_BYTES>>>(particles, weights, bi, bhn); // idx 3 (ncu)

    mlp_layer_t<<<dim3(16, 4, 2), 256>>>(action, time_idx, b1, 288, 0);
    mlp_layer_t<<<dim3(16, 4, 2), 256>>>(action, time_idx, b2, 256, 1);
    mlp_out<<<(2 * BATCH * 32 + 255) / 256, 256>>>(W3, b3, out);
}